// round 16
// baseline (speedup 1.0000x reference)
#include <cuda_runtime.h>
#include <cuda_fp16.h>
#include <cstdint>

#define N_TOK 8192
#define HID   2048
#define NE    8

// ---------------------------------------------------------------------------
// Static device scratch
// ---------------------------------------------------------------------------
__device__ float  g_gate[N_TOK * NE];
__device__ __half g_xh [(size_t)N_TOK * HID];              // x in fp16
__device__ __half g_wth[(size_t)NE * HID * HID];           // W^T fp16 [e][f][h]

// ---------------------------------------------------------------------------
// PTX helpers (baseline sm_80/75-era only)
// ---------------------------------------------------------------------------
__device__ __forceinline__ uint32_t smem_u32(const void* p) {
    uint32_t a;
    asm("{ .reg .u64 t; cvta.to.shared.u64 t, %1; cvt.u32.u64 %0, t; }"
        : "=r"(a) : "l"(p));
    return a;
}
#define CP16(dst, src) \
    asm volatile("cp.async.cg.shared.global [%0], [%1], 16;" \
                 :: "r"(dst), "l"(src) : "memory")
#define CP_COMMIT() asm volatile("cp.async.commit_group;" ::: "memory")
#define CP_WAIT(n)  asm volatile("cp.async.wait_group %0;" :: "n"(n) : "memory")

#define LDSM_X4(r0, r1, r2, r3, a) \
    asm volatile("ldmatrix.sync.aligned.m8n8.x4.shared.b16 {%0,%1,%2,%3}, [%4];" \
                 : "=r"(r0), "=r"(r1), "=r"(r2), "=r"(r3) : "r"(a))

__device__ __forceinline__ void mma16816(float* d, const uint32_t* a,
                                         const uint32_t* bfr) {
    asm volatile(
        "mma.sync.aligned.m16n8k16.row.col.f32.f16.f16.f32 "
        "{%0,%1,%2,%3}, {%4,%5,%6,%7}, {%8,%9}, {%0,%1,%2,%3};"
        : "+f"(d[0]), "+f"(d[1]), "+f"(d[2]), "+f"(d[3])
        : "r"(a[0]), "r"(a[1]), "r"(a[2]), "r"(a[3]), "r"(bfr[0]), "r"(bfr[1]));
}

// ---------------------------------------------------------------------------
// Fused preprocessing kernel. 512 threads, 64KB dynamic smem.
// blockIdx.x % 9 == 0  -> gate block  (512 of them): softmax gate + x->fp16
// else                 -> transpose block (4096): W[e,h,f] fp32 -> Wt[e,f,h] fp16
// Interleaved roles co-schedule both DRAM streams.
// ---------------------------------------------------------------------------
__global__ __launch_bounds__(512)
void prep_kernel(const float* __restrict__ x,
                 const float* __restrict__ W,
                 const float* __restrict__ Wg,
                 const float* __restrict__ bg) {
    extern __shared__ float smf[];
    const int bx   = blockIdx.x;
    const int tid  = threadIdx.x;

    if (bx % 9 == 0) {
        // ---------------- gate + x->fp16 (16 tokens per block) ----------------
        float* Wgs = smf;                 // [NE][HID] = 64KB
        const int wid  = tid >> 5;
        const int lane = tid & 31;
#pragma unroll
        for (int j = 0; j < (HID * NE) / 512; j++) {
            int idx = tid + j * 512;
            int h = idx >> 3, e = idx & 7;
            Wgs[e * HID + h] = Wg[idx];
        }
        __syncthreads();

        const int token = (bx / 9) * 16 + wid;
        const float* xr = x + (size_t)token * HID;
        __half* xo = g_xh + (size_t)token * HID;

        float acc[NE];
#pragma unroll
        for (int e = 0; e < NE; e++) acc[e] = 0.f;

#pragma unroll 4
        for (int k0 = lane * 4; k0 < HID; k0 += 128) {
            float4 xv = *(const float4*)(xr + k0);
            __align__(8) __half hx[4] = {
                __float2half_rn(xv.x), __float2half_rn(xv.y),
                __float2half_rn(xv.z), __float2half_rn(xv.w) };
            *(uint2*)(xo + k0) = *(uint2*)hx;
#pragma unroll
            for (int e = 0; e < NE; e++) {
                float4 w = *(const float4*)&Wgs[e * HID + k0];
                acc[e] += xv.x * w.x + xv.y * w.y + xv.z * w.z + xv.w * w.w;
            }
        }
#pragma unroll
        for (int e = 0; e < NE; e++)
#pragma unroll
            for (int o = 16; o; o >>= 1)
                acc[e] += __shfl_xor_sync(0xFFFFFFFFu, acc[e], o);
        if (lane == 0) {
#pragma unroll
            for (int e = 0; e < NE; e++) acc[e] += bg[e];
            float m = acc[0];
#pragma unroll
            for (int e = 1; e < NE; e++) m = fmaxf(m, acc[e]);
            float s = 0.f, p[NE];
#pragma unroll
            for (int e = 0; e < NE; e++) { p[e] = __expf(acc[e] - m); s += p[e]; }
            float inv = 1.f / s;
            float* gp = &g_gate[(size_t)token * NE];
            *(float4*)(gp)     = make_float4(p[0]*inv, p[1]*inv, p[2]*inv, p[3]*inv);
            *(float4*)(gp + 4) = make_float4(p[4]*inv, p[5]*inv, p[6]*inv, p[7]*inv);
        }
    } else {
        // ---------------- transpose+convert: 128(h) x 64(f) tile --------------
        float (*tile)[65] = (float(*)[65])smf;      // 128 x 65 floats = 33.3KB
        const int t_id = bx - (bx / 9) - 1;         // 0..4095
        const int f_t = t_id & 31;                  // 32 f-tiles
        const int h_t = (t_id >> 5) & 15;           // 16 h-tiles
        const int e   = t_id >> 9;                  // 8 experts
        const int h0 = h_t * 128;
        const int f0 = f_t * 64;

        // load 128 rows x 64 f (16 float4/row), coalesced 256B segments
#pragma unroll
        for (int j = 0; j < 4; j++) {
            int idx4 = tid + j * 512;
            int h  = idx4 >> 4;
            int f4 = idx4 & 15;
            float4 v = *(const float4*)&W[((size_t)e * HID + h0 + h) * HID + f0 + f4 * 4];
            tile[h][f4 * 4 + 0] = v.x;
            tile[h][f4 * 4 + 1] = v.y;
            tile[h][f4 * 4 + 2] = v.z;
            tile[h][f4 * 4 + 3] = v.w;
        }
        __syncthreads();

        // store: f-row r (0..63), h-chunk c (0..15) of 8 halfs = 16B;
        // 16 consecutive threads share r -> 256B contiguous global segments
#pragma unroll
        for (int j = 0; j < 2; j++) {
            int idx = tid + j * 512;
            int r = idx >> 4;
            int c = idx & 15;
            __align__(16) __half hv[8];
#pragma unroll
            for (int q = 0; q < 8; q++)
                hv[q] = __float2half_rn(tile[8 * c + q][r]);
            *(uint4*)&g_wth[((size_t)e * HID + f0 + r) * HID + h0 + 8 * c] = *(uint4*)hv;
        }
    }
}

// ---------------------------------------------------------------------------
// Main mma.sync kernel (fp16 in, fp32 accumulate) — proven R8/R15 structure.
// CTA: 128x128, 8 warps (2x4), warp tile 64x32, BK=32, NSLOT=3 ring,
// single barrier/stage, frag pipelining. 80B row stride. 2 CTAs/SM.
// ---------------------------------------------------------------------------
#define BK 32
#define ROWB 80
#define TILE_B (128 * ROWB)             // 10240
#define STAGE_B (2 * TILE_B)            // 20480
#define NSLOT 3
#define SMEM_MAIN (NSLOT * STAGE_B)     // 61440
#define TOT_ITERS (NE * (HID / BK))     // 512

__global__ __launch_bounds__(256, 2)
void moe_mma_kernel(const float* __restrict__ bias,
                    const float* __restrict__ cached,
                    float* __restrict__ out) {
    extern __shared__ char sm[];
    const uint32_t sbase = smem_u32(sm);

    const int tid  = threadIdx.x;
    const int wid  = tid >> 5;
    const int lane = tid & 31;
    const int n0 = blockIdx.y * 128;
    const int f0 = blockIdx.x * 128;
    const int warp_m = wid >> 2;
    const int warp_n = wid & 3;

    const int lr = tid >> 1;
    const int lc = (tid & 1) * 32;
    const __half* srcA = g_xh + (size_t)(n0 + lr) * HID + (lc >> 1);
    const size_t  bRow = (size_t)(f0 + lr) * HID + (lc >> 1);
    const uint32_t dstOff = (uint32_t)lr * ROWB + lc;

    const uint32_t offA = (uint32_t)(warp_m * 64 + (lane & 15)) * ROWB
                        + (uint32_t)(lane >> 4) * 16;
    const int matb = lane >> 3;
    const uint32_t offB = (uint32_t)(warp_n * 32 + ((matb >> 1) * 8) + (lane & 7)) * ROWB
                        + (uint32_t)(matb & 1) * 16;

    float acc[4][4][4];
#pragma unroll
    for (int i = 0; i < 4; i++)
#pragma unroll
        for (int j = 0; j < 4; j++)
#pragma unroll
            for (int q = 0; q < 4; q++) acc[i][j][q] = 0.f;

    const uint32_t slotAddr[NSLOT] = { sbase, sbase + STAGE_B, sbase + 2 * STAGE_B };

    auto load_stage = [&](int s, uint32_t slot) {
        const int e  = s >> 6;
        const int k0 = (s & 63) * BK;
        const uint32_t st = slot + dstOff;
        const __half* pa = srcA + k0;
        const __half* pb = g_wth + (size_t)e * HID * HID + bRow + k0;
        CP16(st,               pa);  CP16(st + 16,          pa + 8);
        CP16(st + TILE_B,      pb);  CP16(st + TILE_B + 16, pb + 8);
        CP_COMMIT();
    };

    load_stage(0, slotAddr[0]);
    load_stage(1, slotAddr[1]);
    int wslot = 2, rslot = 0;

    for (int s = 0; s < TOT_ITERS; s++) {
        if (s + 1 < TOT_ITERS) { CP_WAIT(1); }
        else                   { CP_WAIT(0); }
        __syncthreads();
        if (s + 2 < TOT_ITERS) {
            load_stage(s + 2, slotAddr[wslot]);
            if (++wslot == NSLOT) wslot = 0;
        }
        const uint32_t stage = slotAddr[rslot];
        if (++rslot == NSLOT) rslot = 0;

        uint32_t bh[16];
#pragma unroll
        for (int ks = 0; ks < 2; ks++) {
            LDSM_X4(bh[8*ks+0], bh[8*ks+1], bh[8*ks+2], bh[8*ks+3],
                    stage + TILE_B + offB + ks * 32);
            LDSM_X4(bh[8*ks+4], bh[8*ks+5], bh[8*ks+6], bh[8*ks+7],
                    stage + TILE_B + offB + 16 * ROWB + ks * 32);
        }
        uint32_t ah[2][4];
        LDSM_X4(ah[0][0], ah[0][1], ah[0][2], ah[0][3], stage + offA);
#pragma unroll
        for (int g = 0; g < 8; g++) {
            const int ks = g >> 2;
            const int mt = g & 3;
            const int cur = g & 1;
            if (g < 7) {
                const int gn = g + 1;
                LDSM_X4(ah[cur ^ 1][0], ah[cur ^ 1][1],
                        ah[cur ^ 1][2], ah[cur ^ 1][3],
                        stage + offA + (gn & 3) * (16 * ROWB) + (gn >> 2) * 32);
            }
#pragma unroll
            for (int nt = 0; nt < 4; nt++)
                mma16816(acc[mt][nt], ah[cur], &bh[8 * ks + 2 * nt]);
        }

        if ((s & 63) == 63) {
            const int e = s >> 6;
#pragma unroll
            for (int nt = 0; nt < 4; nt++) {
                const int col = f0 + warp_n * 32 + nt * 8 + (lane & 3) * 2;
                const float2 bb = *(const float2*)&bias[(size_t)e * HID + col];
                const float2 cc = *(const float2*)&cached[(size_t)e * HID + col];
#pragma unroll
                for (int mt = 0; mt < 4; mt++) {
                    const int row0 = n0 + warp_m * 64 + mt * 16 + (lane >> 2);
                    const float g0 = g_gate[(size_t)row0 * NE + e];
                    const float g1 = g_gate[(size_t)(row0 + 8) * NE + e];
                    float* p0 = out + (size_t)row0 * HID + col;
                    float* p1 = out + (size_t)(row0 + 8) * HID + col;
                    float2 v0, v1;
                    v0.x = g0 * (fmaxf(acc[mt][nt][0] + bb.x, 0.f) + cc.x);
                    v0.y = g0 * (fmaxf(acc[mt][nt][1] + bb.y, 0.f) + cc.y);
                    v1.x = g1 * (fmaxf(acc[mt][nt][2] + bb.x, 0.f) + cc.x);
                    v1.y = g1 * (fmaxf(acc[mt][nt][3] + bb.y, 0.f) + cc.y);
                    if (e == 0) {
                        *(float2*)p0 = v0;
                        *(float2*)p1 = v1;
                    } else {
                        float2 o0 = *(const float2*)p0;
                        float2 o1 = *(const float2*)p1;
                        o0.x += v0.x; o0.y += v0.y;
                        o1.x += v1.x; o1.y += v1.y;
                        *(float2*)p0 = o0;
                        *(float2*)p1 = o1;
                    }
                    acc[mt][nt][0] = 0.f; acc[mt][nt][1] = 0.f;
                    acc[mt][nt][2] = 0.f; acc[mt][nt][3] = 0.f;
                }
            }
        }
    }
}

// ---------------------------------------------------------------------------
// Launch
// inputs: x[8192*2048], W[8*2048*2048], b[8*2048], Wg[2048*8], bg[8], cached[8*2048]
// ---------------------------------------------------------------------------
extern "C" void kernel_launch(void* const* d_in, const int* in_sizes, int n_in,
                              void* d_out, int out_size) {
    const float* x      = (const float*)d_in[0];
    const float* W      = (const float*)d_in[1];
    const float* b      = (const float*)d_in[2];
    const float* Wg     = (const float*)d_in[3];
    const float* bg     = (const float*)d_in[4];
    const float* cached = (const float*)d_in[5];
    float* out = (float*)d_out;

    static bool attr_set = false;
    if (!attr_set) {
        cudaFuncSetAttribute(prep_kernel,
                             cudaFuncAttributeMaxDynamicSharedMemorySize,
                             NE * HID * (int)sizeof(float));
        cudaFuncSetAttribute(moe_mma_kernel,
                             cudaFuncAttributeMaxDynamicSharedMemorySize, SMEM_MAIN);
        attr_set = true;
    }

    // 4096 transpose blocks + 512 gate blocks, interleaved (every 9th = gate)
    prep_kernel<<<4608, 512, NE * HID * sizeof(float)>>>(x, W, Wg, bg);
    moe_mma_kernel<<<dim3(HID / 128, N_TOK / 128), 256, SMEM_MAIN>>>(b, cached, out);
}